// round 6
// baseline (speedup 1.0000x reference)
#include <cuda_runtime.h>

// SparseBiasDiagUnfolder — one wave, 28 warps/CTA, 2 window-rows per warp.
//   adj: (B=2, N=2048, N=2048, F=16) fp32; starts 0,4,...,2040 (511);
//   out (B, 511, 56*16).
//
// 8176 window rows total; 2 rows per warp -> 4088 warps = 146 blocks x 28
// warps exactly (one wave, no remainder). Rows 2w and 2w+1 always share the
// same bs = b*511+s group (8 rows per bs), so the /511 decompose runs once.
// Each row is a 512B contiguous run in adj: lane l loads float4 base+l ->
// 2 independent fully-coalesced LDG.128 batched up front. Stores: 28 active
// lanes per row write a contiguous 448B run (diagonal dropped, repacked).

namespace {
constexpr int N        = 2048;
constexpr int NSTARTS  = 511;
constexpr int NROWS    = 2 * NSTARTS * 8;        // 8176
constexpr int ROWS_PER_WARP = 2;
constexpr int NWARPS   = NROWS / ROWS_PER_WARP;  // 4088
constexpr int WARPS_PER_BLOCK = 28;
constexpr int THREADS  = WARPS_PER_BLOCK * 32;   // 896
constexpr int BLOCKS   = NWARPS / WARPS_PER_BLOCK;  // 146 (exact)
}

__global__ void __launch_bounds__(THREADS)
sparse_diag_unfold_kernel(const float4* __restrict__ adj, float4* __restrict__ out)
{
    const int gt   = blockIdx.x * THREADS + threadIdx.x;
    const int w    = gt >> 5;                 // warp id, 0..4087
    const int lane = gt & 31;

    const int bs      = w >> 2;               // b*511 + s
    const int ii_base = (w & 3) * 2;          // 0,2,4,6
    const int s  = bs % NSTARTS;
    const int b  = bs / NSTARTS;

    // float4 base index of row (bs, ii_base)
    const long base0 = ((long)b * N * N
                      + (long)(4 * s) * (N + 1)
                      + (long)ii_base * N) * 4;

    const int jj = lane >> 2;
    const int v  = lane & 3;

    // 2 independent coalesced 512B loads, batched (MLP_p1 = 2).
    float4 vals[ROWS_PER_WARP];
    #pragma unroll
    for (int k = 0; k < ROWS_PER_WARP; k++)
        vals[k] = adj[base0 + (long)k * (N * 4) + lane];

    const long out_base = (long)bs * 56 * 4;
    #pragma unroll
    for (int k = 0; k < ROWS_PER_WARP; k++) {
        const int ii = ii_base + k;
        if (jj != ii) {
            const int pos = ii * 7 + jj - (jj > ii);   // 0..55
            out[out_base + pos * 4 + v] = vals[k];
        }
    }
}

extern "C" void kernel_launch(void* const* d_in, const int* in_sizes, int n_in,
                              void* d_out, int out_size)
{
    const float4* adj = (const float4*)d_in[0];
    float4* out = (float4*)d_out;
    sparse_diag_unfold_kernel<<<BLOCKS, THREADS>>>(adj, out);
}

// round 7
// speedup vs baseline: 1.0386x; 1.0386x over previous
#include <cuda_runtime.h>

// SparseBiasDiagUnfolder — best-known config (R5: one wave, 146x448,
// 4 window-rows per warp, MLP_p1=4) + cheap index math (no div/mod).
//
//   adj: (B=2, N=2048, N=2048, F=16) fp32; starts 0,4,...,2040 (511);
//   out (B, 511, 56*16).
//
// Warp w (0..2043) covers rows [4w, 4w+4); all share bs = w>>1 (b*511+s).
// bs < 1022 so b = (bs >= 511), s = bs - 511*b  — no integer division.
// Each row is 512B contiguous in adj: lane l loads float4 base+l ->
// 4 independent fully-coalesced LDG.128 batched up front. Stores: per row,
// 28 active lanes write a contiguous 448B run; the warp's 4 rows write one
// contiguous 1792B block of output.

namespace {
constexpr int N        = 2048;
constexpr int NSTARTS  = 511;
constexpr int WARPS_PER_BLOCK = 14;
constexpr int THREADS  = WARPS_PER_BLOCK * 32;   // 448
constexpr int BLOCKS   = 146;                    // 2044 warps = 8176 rows / 4
}

__global__ void __launch_bounds__(THREADS)
sparse_diag_unfold_kernel(const float4* __restrict__ adj, float4* __restrict__ out)
{
    const int gt   = blockIdx.x * THREADS + threadIdx.x;
    const int w    = gt >> 5;                 // 0..2043
    const int lane = gt & 31;

    const int bs      = w >> 1;               // b*511 + s, < 1022
    const int ii_base = (w & 1) * 4;          // 0 or 4

    const int b = (bs >= NSTARTS);            // no division
    const int s = bs - b * NSTARTS;

    // float4 base index of row (bs, ii_base):
    // (b*N*N + 4s*(N+1) + ii_base*N) * 4
    const long base0 = (long)b * (N * N * 4)
                     + (long)s * ((N + 1) * 16)
                     + ii_base * (N * 4)
                     + lane;

    const int jj = lane >> 2;
    const int v  = lane & 3;

    // 4 independent coalesced 512B loads, batched (MLP_p1 = 4).
    float4 vals[4];
    #pragma unroll
    for (int k = 0; k < 4; k++)
        vals[k] = adj[base0 + k * (N * 4)];

    const long out_base = (long)bs * (56 * 4);
    #pragma unroll
    for (int k = 0; k < 4; k++) {
        const int ii = ii_base + k;
        if (jj != ii) {
            const int pos = ii * 7 + jj - (jj > ii);   // 0..55
            out[out_base + pos * 4 + v] = vals[k];
        }
    }
}

extern "C" void kernel_launch(void* const* d_in, const int* in_sizes, int n_in,
                              void* d_out, int out_size)
{
    const float4* adj = (const float4*)d_in[0];
    float4* out = (float4*)d_out;
    sparse_diag_unfold_kernel<<<BLOCKS, THREADS>>>(adj, out);
}